// round 1
// baseline (speedup 1.0000x reference)
#include <cuda_runtime.h>
#include <cstdint>
#include <cstddef>

#define K3   27
#define PPK  131072
#define NVOX 262144
#define CIN  32
#define COUT 32

// ---------- packed f32x2 helpers (Blackwell dual-issue fp32) ----------
__device__ __forceinline__ unsigned long long pack2(float x) {
    unsigned long long r;
    asm("mov.b64 %0, {%1, %1};" : "=l"(r) : "f"(x));
    return r;
}
__device__ __forceinline__ void ffma2(unsigned long long &d,
                                      unsigned long long a,
                                      unsigned long long b) {
    asm("fma.rn.f32x2 %0, %1, %2, %0;" : "+l"(d) : "l"(a), "l"(b));
}
__device__ __forceinline__ void lds_w2(unsigned addr,
                                       unsigned long long &a,
                                       unsigned long long &b) {
    asm("ld.shared.v2.u64 {%0, %1}, [%2];" : "=l"(a), "=l"(b) : "r"(addr));
}
__device__ __forceinline__ void unpack2(unsigned long long v, float &lo, float &hi) {
    asm("mov.b64 {%0, %1}, %2;" : "=f"(lo), "=f"(hi) : "l"(v));
}
// vector reduction to global (no return) — one L2 op per 16B
__device__ __forceinline__ void red4(float* p, float a, float b, float c, float d) {
    asm volatile("red.global.add.v4.f32 [%0], {%1, %2, %3, %4};"
                 :: "l"(p), "f"(a), "f"(b), "f"(c), "f"(d) : "memory");
}

// ---------- out[v][c] = bias[c] ----------
__global__ __launch_bounds__(256) void bias_init_kernel(
    const float* __restrict__ bias, float4* __restrict__ out) {
    int idx = blockIdx.x * 256 + threadIdx.x;   // over NVOX*8 float4s
    float4 b = __ldg(((const float4*)bias) + (idx & 7));
    out[idx] = b;
}

// ---------- main conv: thread handles 2 pairs of one kernel offset ----------
__global__ __launch_bounds__(256) void conv_pairs_kernel(
    const float* __restrict__ in_f,
    const float* __restrict__ Wg,
    const int4*  __restrict__ nbmap4,   // {src0,dst0,src1,dst1}
    float*       __restrict__ out) {

    __shared__ float Ws[CIN * COUT];    // 4 KB: this block's kernel offset
    const int tid = threadIdx.x;
    const int k   = blockIdx.y;

    // 1024 floats = 256 float4 : one per thread
    ((float4*)Ws)[tid] = __ldg((const float4*)(Wg + k * CIN * COUT) + tid);
    __syncthreads();
    const unsigned wsb = (unsigned)__cvta_generic_to_shared(Ws);

    // pair indices: block covers 512 pairs, thread owns pairs (2t, 2t+1)
    const long m0 = (long)k * PPK + (long)blockIdx.x * 512 + tid * 2;
    const int4 mp = __ldg(nbmap4 + (m0 >> 1));   // 16B aligned (m0 even)

    // gather both input rows fully (MLP = 16)
    const float4* r0p = (const float4*)(in_f + (size_t)mp.x * CIN);
    const float4* r1p = (const float4*)(in_f + (size_t)mp.z * CIN);
    float4 A0[8], A1[8];
#pragma unroll
    for (int j = 0; j < 8; j++) { A0[j] = __ldg(r0p + j); A1[j] = __ldg(r1p + j); }

    unsigned long long acc0[16], acc1[16];
#pragma unroll
    for (int j = 0; j < 16; j++) { acc0[j] = 0ull; acc1[j] = 0ull; }

#pragma unroll
    for (int i4 = 0; i4 < 8; i4++) {
        const float e0[4] = {A0[i4].x, A0[i4].y, A0[i4].z, A0[i4].w};
        const float e1[4] = {A1[i4].x, A1[i4].y, A1[i4].z, A1[i4].w};
#pragma unroll
        for (int j = 0; j < 4; j++) {
            const int i = i4 * 4 + j;
            const unsigned long long a0 = pack2(e0[j]);
            const unsigned long long a1 = pack2(e1[j]);
            const unsigned rowb = wsb + i * (COUT * 4);
#pragma unroll
            for (int q = 0; q < 8; q++) {           // 8 x 16B = one W row
                unsigned long long w0, w1;
                lds_w2(rowb + q * 16, w0, w1);      // broadcast LDS.128
                ffma2(acc0[2 * q + 0], a0, w0);
                ffma2(acc0[2 * q + 1], a0, w1);
                ffma2(acc1[2 * q + 0], a1, w0);
                ffma2(acc1[2 * q + 1], a1, w1);
            }
        }
    }

    // scatter-add: 8 x red.v4 per pair
    float* o0 = out + (size_t)mp.y * COUT;
    float* o1 = out + (size_t)mp.w * COUT;
#pragma unroll
    for (int q = 0; q < 8; q++) {
        float x0, x1, y0, y1;
        unpack2(acc0[2 * q + 0], x0, x1);
        unpack2(acc0[2 * q + 1], y0, y1);
        red4(o0 + q * 4, x0, x1, y0, y1);
    }
#pragma unroll
    for (int q = 0; q < 8; q++) {
        float x0, x1, y0, y1;
        unpack2(acc1[2 * q + 0], x0, x1);
        unpack2(acc1[2 * q + 1], y0, y1);
        red4(o1 + q * 4, x0, x1, y0, y1);
    }
}

extern "C" void kernel_launch(void* const* d_in, const int* in_sizes, int n_in,
                              void* d_out, int out_size) {
    const float* in_f  = (const float*)d_in[0];   // [262144, 32] f32
    const float* W     = (const float*)d_in[1];   // [27, 32, 32] f32
    const float* bias  = (const float*)d_in[2];   // [32] f32
    const int*   nbmap = (const int*)d_in[3];     // [M, 2] i32
    float*       out   = (float*)d_out;           // [262144, 32] f32
    (void)in_sizes; (void)n_in; (void)out_size;

    bias_init_kernel<<<(NVOX * 8) / 256, 256>>>(bias, (float4*)out);

    dim3 grid(PPK / 512, K3);
    conv_pairs_kernel<<<grid, 256>>>(in_f, W, (const int4*)nbmap, out);
}

// round 2
// speedup vs baseline: 1.3877x; 1.3877x over previous
#include <cuda_runtime.h>
#include <cstdint>
#include <cstddef>

#define K3   27
#define PPK  131072
#define NVOX 262144
#define CIN  32
#define COUT 32
#define TPB  128      // threads per block
#define TILE 256      // pairs per block tile

// ---------- packed f32x2 helpers ----------
__device__ __forceinline__ unsigned long long pack2(float x) {
    unsigned long long r;
    asm("mov.b64 %0, {%1, %1};" : "=l"(r) : "f"(x));
    return r;
}
__device__ __forceinline__ void ffma2(unsigned long long &d,
                                      unsigned long long a,
                                      unsigned long long b) {
    asm("fma.rn.f32x2 %0, %1, %2, %0;" : "+l"(d) : "l"(a), "l"(b));
}
__device__ __forceinline__ void lds_w2(unsigned addr,
                                       unsigned long long &a,
                                       unsigned long long &b) {
    asm("ld.shared.v2.u64 {%0, %1}, [%2];" : "=l"(a), "=l"(b) : "r"(addr));
}
__device__ __forceinline__ void unpack2(unsigned long long v, float &lo, float &hi) {
    asm("mov.b64 {%0, %1}, %2;" : "=f"(lo), "=f"(hi) : "l"(v));
}
__device__ __forceinline__ void red4(float* p, float a, float b, float c, float d) {
    asm volatile("red.global.add.v4.f32 [%0], {%1, %2, %3, %4};"
                 :: "l"(p), "f"(a), "f"(b), "f"(c), "f"(d) : "memory");
}

// ---------- out[v][c] = bias[c] ----------
__global__ __launch_bounds__(256) void bias_init_kernel(
    const float* __restrict__ bias, float4* __restrict__ out) {
    int idx = blockIdx.x * 256 + threadIdx.x;   // over NVOX*8 float4s
    float4 b = __ldg(((const float4*)bias) + (idx & 7));
    out[idx] = b;
}

// ---------- main conv: block = 256-pair tile of one kernel offset ----------
__global__ __launch_bounds__(TPB) void conv_tile_kernel(
    const float4* __restrict__ in_f4,   // [NVOX*8] float4 (rows of 128B)
    const float*  __restrict__ Wg,      // [27,32,32]
    const int2*   __restrict__ nbmap2,  // [M] {src,dst}
    float*        __restrict__ out) {

    __shared__ float4 A_s[TILE * 8];    // 32 KB: A tile, then reused as C tile
    __shared__ float  W_s[CIN * COUT];  // 4 KB
    __shared__ int    src_s[TILE];
    __shared__ int    dst_s[TILE];

    const int t = threadIdx.x;
    const int k = blockIdx.y;
    const long base = (long)k * PPK + (long)blockIdx.x * TILE;

    // load W[k] (256 float4 across 128 threads)
    {
        const float4* wsrc = (const float4*)(Wg + k * CIN * COUT);
        ((float4*)W_s)[t]       = __ldg(wsrc + t);
        ((float4*)W_s)[t + TPB] = __ldg(wsrc + t + TPB);
    }
    // load nbmap tile
    {
        int2 a = __ldg(nbmap2 + base + t);
        int2 b = __ldg(nbmap2 + base + TPB + t);
        src_s[t]       = a.x; dst_s[t]       = a.y;
        src_s[t + TPB] = b.x; dst_s[t + TPB] = b.y;
    }
    __syncthreads();

    // ---- coalesced gather: 8 lanes per row, 4 rows per warp instr ----
#pragma unroll
    for (int j = 0; j < 16; j++) {
        int idx = j * TPB + t;
        int r = idx >> 3;
        int c = idx & 7;
        int src = src_s[r];
        float4 v = __ldg(in_f4 + (size_t)src * 8 + c);
        A_s[r * 8 + (c ^ (r & 7))] = v;     // XOR-swizzled store
    }
    __syncthreads();

    // ---- compute: thread owns rows t and t+128 ----
    const unsigned wsb = (unsigned)__cvta_generic_to_shared(W_s);
    const int r0 = t, r1 = t + TPB;

    unsigned long long acc0[16], acc1[16];
#pragma unroll
    for (int j = 0; j < 16; j++) { acc0[j] = 0ull; acc1[j] = 0ull; }

#pragma unroll
    for (int i4 = 0; i4 < 8; i4++) {
        float4 a0 = A_s[r0 * 8 + (i4 ^ (r0 & 7))];
        float4 a1 = A_s[r1 * 8 + (i4 ^ (r1 & 7))];
        const float e0[4] = {a0.x, a0.y, a0.z, a0.w};
        const float e1[4] = {a1.x, a1.y, a1.z, a1.w};
#pragma unroll
        for (int j = 0; j < 4; j++) {
            const int i = i4 * 4 + j;
            const unsigned long long p0 = pack2(e0[j]);
            const unsigned long long p1 = pack2(e1[j]);
            const unsigned rowb = wsb + i * (COUT * 4);
#pragma unroll
            for (int q = 0; q < 8; q++) {           // 8 x 16B = one W row
                unsigned long long w0, w1;
                lds_w2(rowb + q * 16, w0, w1);      // broadcast LDS.128
                ffma2(acc0[2 * q + 0], p0, w0);
                ffma2(acc0[2 * q + 1], p0, w1);
                ffma2(acc1[2 * q + 0], p1, w0);
                ffma2(acc1[2 * q + 1], p1, w1);
            }
        }
    }

    // ---- store contributions back into the (now-consumed) A tile ----
    // Safe without sync: thread overwrites only rows r0/r1, which only it reads.
#pragma unroll
    for (int cc = 0; cc < 8; cc++) {
        float x0, x1, y0, y1;
        unpack2(acc0[2 * cc + 0], x0, x1);
        unpack2(acc0[2 * cc + 1], y0, y1);
        A_s[r0 * 8 + (cc ^ (r0 & 7))] = make_float4(x0, x1, y0, y1);
    }
#pragma unroll
    for (int cc = 0; cc < 8; cc++) {
        float x0, x1, y0, y1;
        unpack2(acc1[2 * cc + 0], x0, x1);
        unpack2(acc1[2 * cc + 1], y0, y1);
        A_s[r1 * 8 + (cc ^ (r1 & 7))] = make_float4(x0, x1, y0, y1);
    }
    __syncthreads();

    // ---- coalesced scatter: 8 lanes cover one dst row (1 wavefront/pair) ----
#pragma unroll
    for (int j = 0; j < 16; j++) {
        int idx = j * TPB + t;
        int r = idx >> 3;
        int q = idx & 7;
        int c = q ^ (r & 7);                 // chunk identity under swizzle
        float4 v = A_s[r * 8 + q];
        float* o = out + (size_t)dst_s[r] * COUT + c * 4;
        red4(o, v.x, v.y, v.z, v.w);
    }
}

extern "C" void kernel_launch(void* const* d_in, const int* in_sizes, int n_in,
                              void* d_out, int out_size) {
    const float* in_f  = (const float*)d_in[0];   // [262144, 32] f32
    const float* W     = (const float*)d_in[1];   // [27, 32, 32] f32
    const float* bias  = (const float*)d_in[2];   // [32] f32
    const int*   nbmap = (const int*)d_in[3];     // [M, 2] i32
    float*       out   = (float*)d_out;           // [262144, 32] f32
    (void)in_sizes; (void)n_in; (void)out_size;

    bias_init_kernel<<<(NVOX * 8) / 256, 256>>>(bias, (float4*)out);

    dim3 grid(PPK / TILE, K3);
    conv_tile_kernel<<<grid, TPB>>>((const float4*)in_f, W,
                                    (const int2*)nbmap, out);
}

// round 4
// speedup vs baseline: 1.6679x; 1.2019x over previous
#include <cuda_runtime.h>
#include <cuda_bf16.h>
#include <cstdint>
#include <cstddef>

#define K3   27
#define PPK  131072
#define NVOX 262144
#define CIN  32
#define COUT 32
#define TPB  128      // threads per block (4 warps)
#define TILE 256      // pairs per block tile (warp owns 64 rows)

// ---------- helpers ----------
__device__ __forceinline__ unsigned smem_u32(const void* p) {
    unsigned a;
    asm("{ .reg .u64 t; cvta.to.shared.u64 t, %1; cvt.u32.u64 %0, t; }" : "=r"(a) : "l"(p));
    return a;
}
// pack (a,b) -> bf16x2, a in LOW half
__device__ __forceinline__ unsigned pk_bf2(float a, float b) {
    unsigned r;
    asm("cvt.rn.bf16x2.f32 %0, %1, %2;" : "=r"(r) : "f"(b), "f"(a));
    return r;
}
__device__ __forceinline__ void red4(float* p, float a, float b, float c, float d) {
    asm volatile("red.global.add.v4.f32 [%0], {%1, %2, %3, %4};"
                 :: "l"(p), "f"(a), "f"(b), "f"(c), "f"(d) : "memory");
}
__device__ __forceinline__ void ldsm4(unsigned &r0, unsigned &r1, unsigned &r2, unsigned &r3,
                                      unsigned addr) {
    asm volatile("ldmatrix.sync.aligned.m8n8.x4.shared.b16 {%0,%1,%2,%3}, [%4];"
                 : "=r"(r0), "=r"(r1), "=r"(r2), "=r"(r3) : "r"(addr));
}
__device__ __forceinline__ void mma16816(float c[4],
                                         unsigned a0, unsigned a1, unsigned a2, unsigned a3,
                                         unsigned b0, unsigned b1) {
    asm volatile(
        "mma.sync.aligned.m16n8k16.row.col.f32.bf16.bf16.f32 "
        "{%0,%1,%2,%3}, {%4,%5,%6,%7}, {%8,%9}, {%0,%1,%2,%3};"
        : "+f"(c[0]), "+f"(c[1]), "+f"(c[2]), "+f"(c[3])
        : "r"(a0), "r"(a1), "r"(a2), "r"(a3), "r"(b0), "r"(b1));
}

// Pre-built mma B-fragments: [ko][ng][part(hi/lo)][lane] -> uint4{b0kg0,b1kg0,b0kg1,b1kg1}
__device__ __align__(16) uint4 Wfrag[K3 * 4 * 2 * 32];

// ---------- prep: split W into bf16 hi/lo mma fragments ----------
__global__ __launch_bounds__(256) void prep_W_kernel(const float* __restrict__ Wg) {
    const int ko = blockIdx.x;
    const int e  = threadIdx.x;          // (ng, part, lane)
    const int ng = e >> 6;
    const int part = (e >> 5) & 1;
    const int lane = e & 31;
    const int q = lane & 3;
    const int n = ng * 8 + (lane >> 2);

    unsigned b[4];
#pragma unroll
    for (int kg = 0; kg < 2; kg++) {
        const int k0 = kg * 16 + q * 2;
        float v[4];
        v[0] = __ldg(Wg + ko * 1024 + (k0 + 0) * 32 + n);
        v[1] = __ldg(Wg + ko * 1024 + (k0 + 1) * 32 + n);
        v[2] = __ldg(Wg + ko * 1024 + (k0 + 8) * 32 + n);
        v[3] = __ldg(Wg + ko * 1024 + (k0 + 9) * 32 + n);
        float p[4];
#pragma unroll
        for (int i = 0; i < 4; i++) {
            float hi = __bfloat162float(__float2bfloat16(v[i]));
            p[i] = part ? (v[i] - hi) : hi;
        }
        b[2 * kg + 0] = pk_bf2(p[0], p[1]);
        b[2 * kg + 1] = pk_bf2(p[2], p[3]);
    }
    Wfrag[((ko * 4 + ng) * 2 + part) * 32 + lane] = make_uint4(b[0], b[1], b[2], b[3]);
}

// ---------- out[v][c] = bias[c] ----------
__global__ __launch_bounds__(256) void bias_init_kernel(
    const float* __restrict__ bias, float4* __restrict__ out) {
    int idx = blockIdx.x * 256 + threadIdx.x;
    float4 b = __ldg(((const float4*)bias) + (idx & 7));
    out[idx] = b;
}

// ---------- main conv ----------
__global__ __launch_bounds__(TPB) void conv_mma_kernel(
    const float4* __restrict__ in_f4,
    const int2*   __restrict__ nbmap2,
    float*        __restrict__ out) {

    __shared__ __align__(128) char A_s[TILE * 128];   // 32KB: bf16 hi|lo rows, swizzled
    __shared__ int src_s[TILE];
    __shared__ int dst_s[TILE];

    const int t = threadIdx.x;
    const int lane = t & 31;
    const int wid = t >> 5;
    const int ko = blockIdx.y;
    const long base = (long)ko * PPK + (long)blockIdx.x * TILE;

    // nbmap tile
    {
        int2 a = __ldg(nbmap2 + base + t);
        int2 b = __ldg(nbmap2 + base + TPB + t);
        src_s[t] = a.x; dst_s[t] = a.y;
        src_s[t + TPB] = b.x; dst_s[t + TPB] = b.y;
    }

    // B fragments for this kernel offset (held in registers whole kernel)
    unsigned bh[4][4], bl[4][4];
#pragma unroll
    for (int ng = 0; ng < 4; ng++) {
        uint4 h = __ldg(&Wfrag[((ko * 4 + ng) * 2 + 0) * 32 + lane]);
        uint4 l = __ldg(&Wfrag[((ko * 4 + ng) * 2 + 1) * 32 + lane]);
        bh[ng][0] = h.x; bh[ng][1] = h.y; bh[ng][2] = h.z; bh[ng][3] = h.w;
        bl[ng][0] = l.x; bl[ng][1] = l.y; bl[ng][2] = l.z; bl[ng][3] = l.w;
    }
    __syncthreads();

    // ---- coalesced gather + bf16 split + swizzled STS ----
#pragma unroll
    for (int j = 0; j < 16; j++) {
        int idx = j * TPB + t;           // 2048 = 256 rows x 8 float4-chunks
        int r = idx >> 3;
        int c = idx & 7;
        float4 v = __ldg(in_f4 + (size_t)src_s[r] * 8 + c);
        unsigned h01 = pk_bf2(v.x, v.y);
        unsigned h23 = pk_bf2(v.z, v.w);
        float hx = __uint_as_float(h01 << 16);
        float hy = __uint_as_float(h01 & 0xffff0000u);
        float hz = __uint_as_float(h23 << 16);
        float hw = __uint_as_float(h23 & 0xffff0000u);
        unsigned l01 = pk_bf2(v.x - hx, v.y - hy);
        unsigned l23 = pk_bf2(v.z - hz, v.w - hw);
        // hi chunk = c>>1 (k block), lo chunk = 4 + (c>>1); XOR-swizzle by row
        int hc = (c >> 1) ^ (r & 7);
        int lc = ((c >> 1) | 4) ^ (r & 7);
        int sub = (c & 1) * 8;
        *(uint2*)(A_s + r * 128 + hc * 16 + sub) = make_uint2(h01, h23);
        *(uint2*)(A_s + r * 128 + lc * 16 + sub) = make_uint2(l01, l23);
    }
    __syncthreads();

    const unsigned asb = smem_u32(A_s);
    // ldmatrix lane mapping
    const int mrow = ((lane >> 3) & 1) * 8 + (lane & 7);
    const int csel = lane >> 4;          // 0: k-low 8, 1: k-high 8
    const int qr = lane >> 2;            // C frag row-within-8
    const int qq = lane & 3;             // C frag col quad

#pragma unroll
    for (int half = 0; half < 2; half++) {
        const int rbase = wid * 64 + half * 32;

        float c[2][4][4];
#pragma unroll
        for (int mg = 0; mg < 2; mg++)
#pragma unroll
            for (int ng = 0; ng < 4; ng++)
#pragma unroll
                for (int i = 0; i < 4; i++) c[mg][ng][i] = 0.0f;

#pragma unroll
        for (int kg = 0; kg < 2; kg++) {
            unsigned ah[2][4], al[2][4];
#pragma unroll
            for (int mg = 0; mg < 2; mg++) {
                int row = rbase + mg * 16 + mrow;
                unsigned ro = asb + row * 128;
                int hchunk = 2 * kg + csel;
                ldsm4(ah[mg][0], ah[mg][1], ah[mg][2], ah[mg][3],
                      ro + ((hchunk ^ (row & 7)) << 4));
                ldsm4(al[mg][0], al[mg][1], al[mg][2], al[mg][3],
                      ro + (((hchunk + 4) ^ (row & 7)) << 4));
            }
#pragma unroll
            for (int mg = 0; mg < 2; mg++)
#pragma unroll
                for (int ng = 0; ng < 4; ng++) {
                    unsigned b0 = bh[ng][2 * kg], b1 = bh[ng][2 * kg + 1];
                    mma16816(c[mg][ng], ah[mg][0], ah[mg][1], ah[mg][2], ah[mg][3], b0, b1);
                    mma16816(c[mg][ng], al[mg][0], al[mg][1], al[mg][2], al[mg][3], b0, b1);
                    mma16816(c[mg][ng], ah[mg][0], ah[mg][1], ah[mg][2], ah[mg][3],
                             bl[ng][2 * kg], bl[ng][2 * kg + 1]);
                }
        }

        __syncwarp();
        // ---- store C frags into (consumed) A rows, swizzled ----
#pragma unroll
        for (int mg = 0; mg < 2; mg++) {
#pragma unroll
            for (int ng = 0; ng < 4; ng++) {
                int r0 = rbase + mg * 16 + qr;
                int r1 = r0 + 8;
                int chunk = ng * 2 + (qq >> 1);
                int sub = (qq & 1) * 8;
                *(float2*)(A_s + r0 * 128 + ((chunk ^ (r0 & 7)) << 4) + sub) =
                    make_float2(c[mg][ng][0], c[mg][ng][1]);
                *(float2*)(A_s + r1 * 128 + ((chunk ^ (r1 & 7)) << 4) + sub) =
                    make_float2(c[mg][ng][2], c[mg][ng][3]);
            }
        }
        __syncwarp();

        // ---- coalesced scatter: 8 lanes cover one 128B dst row ----
#pragma unroll
        for (int j = 0; j < 8; j++) {
            int idx = j * 32 + lane;     // 256 = 32 rows x 8 chunks
            int row = rbase + (idx >> 3);
            int q = idx & 7;
            int cc = q ^ (row & 7);
            float4 v = *(const float4*)(A_s + row * 128 + q * 16);
            red4(out + (size_t)dst_s[row] * COUT + cc * 4, v.x, v.y, v.z, v.w);
        }
        __syncwarp();
    }
}

extern "C" void kernel_launch(void* const* d_in, const int* in_sizes, int n_in,
                              void* d_out, int out_size) {
    const float* in_f  = (const float*)d_in[0];   // [262144, 32] f32
    const float* W     = (const float*)d_in[1];   // [27, 32, 32] f32
    const float* bias  = (const float*)d_in[2];   // [32] f32
    const int*   nbmap = (const int*)d_in[3];     // [M, 2] i32
    float*       out   = (float*)d_out;           // [262144, 32] f32
    (void)in_sizes; (void)n_in; (void)out_size;

    prep_W_kernel<<<K3, 256>>>(W);
    bias_init_kernel<<<(NVOX * 8) / 256, 256>>>(bias, (float4*)out);

    dim3 grid(PPK / TILE, K3);
    conv_mma_kernel<<<grid, TPB>>>((const float4*)in_f, (const int2*)nbmap, out);
}

// round 5
// speedup vs baseline: 1.9470x; 1.1673x over previous
#include <cuda_runtime.h>
#include <cuda_bf16.h>
#include <cstdint>
#include <cstddef>

#define K3   27
#define PPK  131072
#define NVOX 262144
#define CIN  32
#define COUT 32
#define TPB  128      // threads per block (4 warps)
#define TILE 128      // pairs per block tile (warp owns 32 rows)

// ---------- helpers ----------
__device__ __forceinline__ unsigned smem_u32(const void* p) {
    unsigned a;
    asm("{ .reg .u64 t; cvta.to.shared.u64 t, %1; cvt.u32.u64 %0, t; }" : "=r"(a) : "l"(p));
    return a;
}
// pack (a,b) -> bf16x2, a in LOW half
__device__ __forceinline__ unsigned pk_bf2(float a, float b) {
    unsigned r;
    asm("cvt.rn.bf16x2.f32 %0, %1, %2;" : "=r"(r) : "f"(b), "f"(a));
    return r;
}
__device__ __forceinline__ void red4(float* p, float a, float b, float c, float d) {
    asm volatile("red.global.add.v4.f32 [%0], {%1, %2, %3, %4};"
                 :: "l"(p), "f"(a), "f"(b), "f"(c), "f"(d) : "memory");
}
__device__ __forceinline__ void ldsm4(unsigned &r0, unsigned &r1, unsigned &r2, unsigned &r3,
                                      unsigned addr) {
    asm volatile("ldmatrix.sync.aligned.m8n8.x4.shared.b16 {%0,%1,%2,%3}, [%4];"
                 : "=r"(r0), "=r"(r1), "=r"(r2), "=r"(r3) : "r"(addr));
}
__device__ __forceinline__ void mma16816(float c[4],
                                         unsigned a0, unsigned a1, unsigned a2, unsigned a3,
                                         unsigned b0, unsigned b1) {
    asm volatile(
        "mma.sync.aligned.m16n8k16.row.col.f32.bf16.bf16.f32 "
        "{%0,%1,%2,%3}, {%4,%5,%6,%7}, {%8,%9}, {%0,%1,%2,%3};"
        : "+f"(c[0]), "+f"(c[1]), "+f"(c[2]), "+f"(c[3])
        : "r"(a0), "r"(a1), "r"(a2), "r"(a3), "r"(b0), "r"(b1));
}

// Pre-built mma B-fragments: [ko][ng][part(hi/lo)][lane] -> uint4{b0kg0,b1kg0,b0kg1,b1kg1}
__device__ __align__(16) uint4 Wfrag[K3 * 4 * 2 * 32];

// ---------- prep: split W into bf16 hi/lo mma fragments ----------
__global__ __launch_bounds__(256) void prep_W_kernel(const float* __restrict__ Wg) {
    const int ko = blockIdx.x;
    const int e  = threadIdx.x;          // (ng, part, lane)
    const int ng = e >> 6;
    const int part = (e >> 5) & 1;
    const int lane = e & 31;
    const int q = lane & 3;
    const int n = ng * 8 + (lane >> 2);

    unsigned b[4];
#pragma unroll
    for (int kg = 0; kg < 2; kg++) {
        const int k0 = kg * 16 + q * 2;
        float v[4];
        v[0] = __ldg(Wg + ko * 1024 + (k0 + 0) * 32 + n);
        v[1] = __ldg(Wg + ko * 1024 + (k0 + 1) * 32 + n);
        v[2] = __ldg(Wg + ko * 1024 + (k0 + 8) * 32 + n);
        v[3] = __ldg(Wg + ko * 1024 + (k0 + 9) * 32 + n);
        float p[4];
#pragma unroll
        for (int i = 0; i < 4; i++) {
            float hi = __bfloat162float(__float2bfloat16(v[i]));
            p[i] = part ? (v[i] - hi) : hi;
        }
        b[2 * kg + 0] = pk_bf2(p[0], p[1]);
        b[2 * kg + 1] = pk_bf2(p[2], p[3]);
    }
    Wfrag[((ko * 4 + ng) * 2 + part) * 32 + lane] = make_uint4(b[0], b[1], b[2], b[3]);
}

// ---------- out[v][c] = bias[c] ----------
__global__ __launch_bounds__(256) void bias_init_kernel(
    const float* __restrict__ bias, float4* __restrict__ out) {
    int idx = blockIdx.x * 256 + threadIdx.x;
    float4 b = __ldg(((const float4*)bias) + (idx & 7));
    out[idx] = b;
}

// ---------- main conv ----------
__global__ __launch_bounds__(TPB, 6) void conv_mma_kernel(
    const float4* __restrict__ in_f4,
    const int2*   __restrict__ nbmap2,
    float*        __restrict__ out) {

    __shared__ __align__(128) char A_s[TILE * 128];   // 16KB: bf16 hi|lo rows, swizzled
    __shared__ int src_s[TILE];
    __shared__ int dst_s[TILE];

    const int t = threadIdx.x;
    const int lane = t & 31;
    const int wid = t >> 5;
    const int ko = blockIdx.y;
    const long base = (long)ko * PPK + (long)blockIdx.x * TILE;

    // nbmap tile
    {
        int2 a = __ldg(nbmap2 + base + t);
        src_s[t] = a.x; dst_s[t] = a.y;
    }

    // B fragments for this kernel offset (held in registers whole kernel)
    unsigned bh[4][4], bl[4][4];
#pragma unroll
    for (int ng = 0; ng < 4; ng++) {
        uint4 h = __ldg(&Wfrag[((ko * 4 + ng) * 2 + 0) * 32 + lane]);
        uint4 l = __ldg(&Wfrag[((ko * 4 + ng) * 2 + 1) * 32 + lane]);
        bh[ng][0] = h.x; bh[ng][1] = h.y; bh[ng][2] = h.z; bh[ng][3] = h.w;
        bl[ng][0] = l.x; bl[ng][1] = l.y; bl[ng][2] = l.z; bl[ng][3] = l.w;
    }
    __syncthreads();

    // ---- coalesced gather + bf16 split + swizzled STS ----
#pragma unroll
    for (int j = 0; j < 8; j++) {
        int idx = j * TPB + t;           // 1024 = 128 rows x 8 float4-chunks
        int r = idx >> 3;
        int c = idx & 7;
        float4 v = __ldg(in_f4 + (size_t)src_s[r] * 8 + c);
        unsigned h01 = pk_bf2(v.x, v.y);
        unsigned h23 = pk_bf2(v.z, v.w);
        float hx = __uint_as_float(h01 << 16);
        float hy = __uint_as_float(h01 & 0xffff0000u);
        float hz = __uint_as_float(h23 << 16);
        float hw = __uint_as_float(h23 & 0xffff0000u);
        unsigned l01 = pk_bf2(v.x - hx, v.y - hy);
        unsigned l23 = pk_bf2(v.z - hz, v.w - hw);
        // hi chunk = c>>1 (k block), lo chunk = 4 + (c>>1); XOR-swizzle by row
        int hc = (c >> 1) ^ (r & 7);
        int lc = ((c >> 1) | 4) ^ (r & 7);
        int sub = (c & 1) * 8;
        *(uint2*)(A_s + r * 128 + hc * 16 + sub) = make_uint2(h01, h23);
        *(uint2*)(A_s + r * 128 + lc * 16 + sub) = make_uint2(l01, l23);
    }
    __syncthreads();

    const unsigned asb = smem_u32(A_s);
    // ldmatrix lane mapping
    const int mrow = ((lane >> 3) & 1) * 8 + (lane & 7);
    const int csel = lane >> 4;          // 0: k-low 8, 1: k-high 8
    const int qr = lane >> 2;            // C frag row-within-8
    const int qq = lane & 3;             // C frag col quad

#pragma unroll
    for (int mg = 0; mg < 2; mg++) {
        const int mgbase = wid * 32 + mg * 16;

        float c[4][4];
#pragma unroll
        for (int ng = 0; ng < 4; ng++)
#pragma unroll
            for (int i = 0; i < 4; i++) c[ng][i] = 0.0f;

#pragma unroll
        for (int kg = 0; kg < 2; kg++) {
            unsigned ah[4], al[4];
            {
                int row = mgbase + mrow;
                unsigned ro = asb + row * 128;
                int hchunk = 2 * kg + csel;
                ldsm4(ah[0], ah[1], ah[2], ah[3], ro + ((hchunk ^ (row & 7)) << 4));
                ldsm4(al[0], al[1], al[2], al[3], ro + (((hchunk + 4) ^ (row & 7)) << 4));
            }
#pragma unroll
            for (int ng = 0; ng < 4; ng++) {
                unsigned b0 = bh[ng][2 * kg], b1 = bh[ng][2 * kg + 1];
                mma16816(c[ng], ah[0], ah[1], ah[2], ah[3], b0, b1);
                mma16816(c[ng], al[0], al[1], al[2], al[3], b0, b1);
                mma16816(c[ng], ah[0], ah[1], ah[2], ah[3],
                         bl[ng][2 * kg], bl[ng][2 * kg + 1]);
            }
        }

        __syncwarp();
        // ---- store C frags into (consumed) A rows of this mg-group ----
#pragma unroll
        for (int ng = 0; ng < 4; ng++) {
            int r0 = mgbase + qr;
            int r1 = r0 + 8;
            int chunk = ng * 2 + (qq >> 1);
            int sub = (qq & 1) * 8;
            *(float2*)(A_s + r0 * 128 + ((chunk ^ (r0 & 7)) << 4) + sub) =
                make_float2(c[ng][0], c[ng][1]);
            *(float2*)(A_s + r1 * 128 + ((chunk ^ (r1 & 7)) << 4) + sub) =
                make_float2(c[ng][2], c[ng][3]);
        }
        __syncwarp();

        // ---- coalesced scatter: 8 lanes cover one 128B dst row ----
#pragma unroll
        for (int j = 0; j < 4; j++) {
            int idx = j * 32 + lane;     // 128 = 16 rows x 8 chunks
            int row = mgbase + (idx >> 3);
            int q = idx & 7;
            int cc = q ^ (row & 7);
            float4 v = *(const float4*)(A_s + row * 128 + q * 16);
            red4(out + (size_t)dst_s[row] * COUT + cc * 4, v.x, v.y, v.z, v.w);
        }
        __syncwarp();
    }
}

extern "C" void kernel_launch(void* const* d_in, const int* in_sizes, int n_in,
                              void* d_out, int out_size) {
    const float* in_f  = (const float*)d_in[0];   // [262144, 32] f32
    const float* W     = (const float*)d_in[1];   // [27, 32, 32] f32
    const float* bias  = (const float*)d_in[2];   // [32] f32
    const int*   nbmap = (const int*)d_in[3];     // [M, 2] i32
    float*       out   = (float*)d_out;           // [262144, 32] f32
    (void)in_sizes; (void)n_in; (void)out_size;

    prep_W_kernel<<<K3, 256>>>(W);
    bias_init_kernel<<<(NVOX * 8) / 256, 256>>>(bias, (float4*)out);

    dim3 grid(PPK / TILE, K3);
    conv_mma_kernel<<<grid, TPB>>>((const float4*)in_f, (const int2*)nbmap, out);
}